// round 5
// baseline (speedup 1.0000x reference)
#include <cuda_runtime.h>
#include <math.h>
#include <stdint.h>

// ---------------- problem constants ----------------
#define B_    2
#define L_    1024
#define E_    768
#define NST   16
#define KC    4
#define R_    48
#define P_    80          // R + 2N
#define H_    3072
#define V_    32000
#define DEP   4
#define ML    (B_*L_)     // 2048 rows

// ---------------- scratch (static device, no allocs) ----------------
__device__ float g_x  [ML*E_];
__device__ float g_xn [ML*E_];
__device__ float g_z  [ML*E_];
__device__ float g_dt [ML*E_];
__device__ float g_u  [ML*E_];
__device__ float g_y  [ML*E_];
__device__ float g_p  [ML*P_];
__device__ float g_hid[ML*H_];
__device__ float g_semb[B_*E_];
__device__ float g_thid[B_*H_];
__device__ float g_temb[B_*E_];

// ---------------- helpers ----------------
__device__ __forceinline__ float silu_f(float x)  { return x / (1.f + expf(-x)); }
__device__ __forceinline__ float gelu_f(float x)  { return 0.5f * x * (1.f + erff(x * 0.70710678118654752f)); }
__device__ __forceinline__ float softplus_f(float x) { return (x > 20.f) ? x : log1pf(expf(x)); }

// packed f32x2 ops (Blackwell sm_103a)
__device__ __forceinline__ uint64_t pack2(float lo, float hi) {
    uint64_t r;
    asm("mov.b64 %0, {%1, %2};" : "=l"(r) : "f"(lo), "f"(hi));
    return r;
}
__device__ __forceinline__ void fma2(uint64_t& d, uint64_t a, uint64_t b) {
    asm("fma.rn.f32x2 %0, %1, %2, %0;" : "+l"(d) : "l"(a), "l"(b));
}
__device__ __forceinline__ void unpack2(uint64_t v, float& lo, float& hi) {
    asm("mov.b64 {%0, %1}, %2;" : "=f"(lo), "=f"(hi) : "l"(v));
}

// ---------------- sinusoidal time embedding ----------------
__global__ void k_semb(const int* __restrict__ ts, float* __restrict__ semb) {
    int idx = blockIdx.x * blockDim.x + threadIdx.x;
    if (idx >= B_ * E_) return;
    int b = idx / E_, e = idx % E_;
    float t = (float)ts[b];
    const int half = E_ / 2;
    float v;
    if (e < half) {
        float f = expf(-logf(10000.f) * (float)e / (float)half);
        v = sinf(t * f);
    } else {
        float f = expf(-logf(10000.f) * (float)(e - half) / (float)half);
        v = cosf(t * f);
    }
    semb[idx] = v;
}

__global__ void k_time1(const float* __restrict__ semb, const float* __restrict__ w1,
                        const float* __restrict__ b1, float* __restrict__ hid) {
    int idx = blockIdx.x * blockDim.x + threadIdx.x;
    if (idx >= B_ * H_) return;
    int b = idx / H_, h = idx % H_;
    const float* sr = semb + b * E_;
    const float* wr = w1 + (long)h * E_;
    float s = b1[h];
    for (int e = 0; e < E_; e++) s += sr[e] * wr[e];
    hid[idx] = silu_f(s);
}

__global__ void k_time2(const float* __restrict__ hid, const float* __restrict__ w2,
                        const float* __restrict__ b2, float* __restrict__ temb) {
    int idx = blockIdx.x * blockDim.x + threadIdx.x;
    if (idx >= B_ * E_) return;
    int b = idx / E_, e = idx % E_;
    const float* hr = hid + b * H_;
    const float* wr = w2 + (long)e * H_;
    float s = b2[e];
    for (int h = 0; h < H_; h++) s += hr[h] * wr[h];
    temb[idx] = s;
}

__global__ void k_embed(const int* __restrict__ tok, const float* __restrict__ emb,
                        const float* __restrict__ temb, float* __restrict__ x) {
    long idx = (long)blockIdx.x * blockDim.x + threadIdx.x;
    if (idx >= (long)ML * E_) return;
    int e  = (int)(idx % E_);
    int bl = (int)(idx / E_);
    int b  = bl / L_;
    int t  = tok[bl];
    x[idx] = emb[(long)t * E_ + e] + temb[b * E_ + e];
}

// ---------------- layer norm (one row per block) ----------------
__global__ void k_ln(const float* __restrict__ x, const float* __restrict__ g,
                     const float* __restrict__ bta, float* __restrict__ o) {
    __shared__ float red[256];
    int row = blockIdx.x;
    int tid = threadIdx.x;
    const float* xr = x + (long)row * E_;
    float v[3];
    float s = 0.f;
#pragma unroll
    for (int i = 0; i < 3; i++) { v[i] = xr[tid + i * 256]; s += v[i]; }
    red[tid] = s; __syncthreads();
    for (int st = 128; st > 0; st >>= 1) { if (tid < st) red[tid] += red[tid + st]; __syncthreads(); }
    float mu = red[0] / (float)E_;
    __syncthreads();
    float s2 = 0.f;
#pragma unroll
    for (int i = 0; i < 3; i++) { float d = v[i] - mu; s2 += d * d; }
    red[tid] = s2; __syncthreads();
    for (int st = 128; st > 0; st >>= 1) { if (tid < st) red[tid] += red[tid + st]; __syncthreads(); }
    float rs = rsqrtf(red[0] / (float)E_ + 1e-5f);
    float* orow = o + (long)row * E_;
#pragma unroll
    for (int i = 0; i < 3; i++) {
        int c = tid + i * 256;
        orow[c] = (v[i] - mu) * rs * g[c] + bta[c];
    }
}

// ---------------- depthwise causal conv (K=4) + SiLU ----------------
__global__ void k_conv_silu(const float* __restrict__ xn, const float* __restrict__ w,
                            float* __restrict__ u) {
    long idx = (long)blockIdx.x * blockDim.x + threadIdx.x;
    if (idx >= (long)ML * E_) return;
    int e  = (int)(idx % E_);
    int bl = (int)(idx / E_);
    int l  = bl % L_;
    const float* xp = xn + idx;   // (b,l,e)
    float s = 0.f;
#pragma unroll
    for (int k = 0; k < KC; k++) {
        int ll = l - (KC - 1) + k;
        if (ll >= 0) s += w[e * KC + k] * xp[(long)(k - (KC - 1)) * E_];
    }
    u[idx] = silu_f(s);
}

// ---------------- SSM scan: 16 threads per (b,e) channel, 1 state each ----------------
// recurrence per reference: h[0]=B[0]*u[0]; h[t]=A[t-1]*h[t-1]+B[t-1]*u[t-1]
// y[t] = C[t] . h[t] + u[t]*D, then gated by silu(z[t]).
__global__ void k_scan(const float* __restrict__ dt, const float* __restrict__ u,
                       const float* __restrict__ p,  const float* __restrict__ z,
                       const float* __restrict__ A_log, const float* __restrict__ Dp,
                       float* __restrict__ y) {
    int tid = blockIdx.x * blockDim.x + threadIdx.x;
    if (tid >= B_ * E_ * NST) return;
    int g  = tid & 15;          // state index 0..15
    int ch = tid >> 4;
    int e  = ch % E_;
    int b  = ch / E_;

    float Av  = -expf(A_log[e * NST + g]);
    float iAv = 1.f / (Av + 1e-10f);
    bool  smA = fabsf(Av) < 1e-5f;
    float Dv  = Dp[e];

    const float* dtp = dt + (long)b * L_ * E_ + e;
    const float* up  = u  + (long)b * L_ * E_ + e;
    const float* zp  = z  + (long)b * L_ * E_ + e;
    const float* cp  = p  + (long)b * L_ * P_ + (R_ + NST) + g;  // Cp[t, g]
    float*       yp  = y  + (long)b * L_ * E_ + e;

    float cd = dtp[0];
    float cu = up[0];
    float cz = zp[0];
    float ccv = cp[0];

    float a  = __expf(cd * Av);
    float bv = smA ? cd : (a - 1.f) * iAv;
    float h  = bv * cu;

    float s = ccv * h;
    s += __shfl_xor_sync(0xffffffffu, s, 1);
    s += __shfl_xor_sync(0xffffffffu, s, 2);
    s += __shfl_xor_sync(0xffffffffu, s, 4);
    s += __shfl_xor_sync(0xffffffffu, s, 8);
    if (g == 0) yp[0] = (s + cu * Dv) * silu_f(cz);
    float pu = cu;

    for (int t = 1; t < L_; t++) {
        // loads for step t (independent of the recurrence -> run ahead)
        float nd = dtp[(long)t * E_];
        float nu = up [(long)t * E_];
        float nz = zp [(long)t * E_];
        float nc = cp [(long)t * P_];
        // h_t = A(dt[t-1]) * h_{t-1} + B(dt[t-1]) * u[t-1]
        h = fmaf(a, h, bv * pu);
        float sv = nc * h;
        sv += __shfl_xor_sync(0xffffffffu, sv, 1);
        sv += __shfl_xor_sync(0xffffffffu, sv, 2);
        sv += __shfl_xor_sync(0xffffffffu, sv, 4);
        sv += __shfl_xor_sync(0xffffffffu, sv, 8);
        if (g == 0) yp[(long)t * E_] = (sv + nu * Dv) * silu_f(nz);
        pu = nu;
        // A/B from dt[t] for the next step
        a  = __expf(nd * Av);
        bv = smA ? nd : (a - 1.f) * iAv;
    }
}

// ============ big-tile SGEMM: 128x128x16, 8x8 microtile, double buffered, f32x2 FMA ============
// C[m,n] = sum_k A[m*lda+k] * W[n*ldw+k]
// Requires: M % 128 == 0, N % 128 == 0, Kd % 16 == 0.
// EPI: 0=none, 2=x+res, 3=gelu(x+bias), 4=x+bias+res, 5=x+bias
#define SPITCH 140   // floats per k-row in smem (560 B, 16B-multiple; +4 shifts banks)
#define KTILE  16
template <int EPI>
__global__ void __launch_bounds__(256, 2) k_gemm128(const float* __restrict__ A, int lda,
                                                    const float* __restrict__ W, int ldw,
                                                    const float* __restrict__ bias,
                                                    const float* __restrict__ res,
                                                    float* __restrict__ C,
                                                    int M, int N, int Kd) {
    __shared__ __align__(16) float As[2][KTILE * SPITCH];
    __shared__ __align__(16) float Bs[2][KTILE * SPITCH];
    const int bm = blockIdx.y * 128;
    const int bn = blockIdx.x * 128;
    const int tid = threadIdx.x;

    // gmem load mapping: each thread loads 8 contiguous floats (2x float4) of A and of W per k-tile
    const int lr  = tid >> 1;          // 0..127 (row within tile)
    const int lk8 = (tid & 1) * 8;     // 0 or 8  (k offset)
    const float* Ap = A + (long)(bm + lr) * lda + lk8;
    const float* Wp = W + (long)(bn + lr) * ldw + lk8;

    // compute mapping: 16x16 threads, 8x8 microtile
    const int tx = tid & 15;           // n-group
    const int ty = tid >> 4;           // m-group
    const int moff = ty * 8;
    const int noff = tx * 8;

    uint64_t acc2[8][4];               // 8 rows x 4 packed f32x2 pairs
#pragma unroll
    for (int i = 0; i < 8; i++)
#pragma unroll
        for (int j = 0; j < 4; j++) acc2[i][j] = 0ull;

    // prologue: load k-tile 0
    float4 av0 = *(const float4*)Ap;
    float4 av1 = *(const float4*)(Ap + 4);
    float4 wv0 = *(const float4*)Wp;
    float4 wv1 = *(const float4*)(Wp + 4);
    {
        float* as = &As[0][lk8 * SPITCH + lr];
        float* bs = &Bs[0][lk8 * SPITCH + lr];
        as[0*SPITCH] = av0.x; as[1*SPITCH] = av0.y; as[2*SPITCH] = av0.z; as[3*SPITCH] = av0.w;
        as[4*SPITCH] = av1.x; as[5*SPITCH] = av1.y; as[6*SPITCH] = av1.z; as[7*SPITCH] = av1.w;
        bs[0*SPITCH] = wv0.x; bs[1*SPITCH] = wv0.y; bs[2*SPITCH] = wv0.z; bs[3*SPITCH] = wv0.w;
        bs[4*SPITCH] = wv1.x; bs[5*SPITCH] = wv1.y; bs[6*SPITCH] = wv1.z; bs[7*SPITCH] = wv1.w;
    }
    __syncthreads();

    int buf = 0;
    const int ntiles = Kd / KTILE;
    for (int kt = 0; kt < ntiles; kt++) {
        // prefetch next tile into registers
        if (kt + 1 < ntiles) {
            const float* Ap2 = Ap + (kt + 1) * KTILE;
            const float* Wp2 = Wp + (kt + 1) * KTILE;
            av0 = *(const float4*)Ap2;  av1 = *(const float4*)(Ap2 + 4);
            wv0 = *(const float4*)Wp2;  wv1 = *(const float4*)(Wp2 + 4);
        }
        // compute current tile
#pragma unroll
        for (int kk = 0; kk < KTILE; kk++) {
            const float* asr = &As[buf][kk * SPITCH];
            const float* bsr = &Bs[buf][kk * SPITCH];
            float4 a0 = *(const float4*)(asr + moff);
            float4 a1 = *(const float4*)(asr + moff + 4);
            ulonglong2 bb0 = *(const ulonglong2*)(bsr + noff);      // pairs {n0,n1},{n2,n3}
            ulonglong2 bb1 = *(const ulonglong2*)(bsr + noff + 4);  // pairs {n4,n5},{n6,n7}
            uint64_t bn2[4] = {bb0.x, bb0.y, bb1.x, bb1.y};
            float am[8] = {a0.x, a0.y, a0.z, a0.w, a1.x, a1.y, a1.z, a1.w};
#pragma unroll
            for (int i = 0; i < 8; i++) {
                uint64_t aii = pack2(am[i], am[i]);
#pragma unroll
                for (int j = 0; j < 4; j++) fma2(acc2[i][j], aii, bn2[j]);
            }
        }
        // store prefetched tile
        if (kt + 1 < ntiles) {
            buf ^= 1;
            float* as = &As[buf][lk8 * SPITCH + lr];
            float* bs = &Bs[buf][lk8 * SPITCH + lr];
            as[0*SPITCH] = av0.x; as[1*SPITCH] = av0.y; as[2*SPITCH] = av0.z; as[3*SPITCH] = av0.w;
            as[4*SPITCH] = av1.x; as[5*SPITCH] = av1.y; as[6*SPITCH] = av1.z; as[7*SPITCH] = av1.w;
            bs[0*SPITCH] = wv0.x; bs[1*SPITCH] = wv0.y; bs[2*SPITCH] = wv0.z; bs[3*SPITCH] = wv0.w;
            bs[4*SPITCH] = wv1.x; bs[5*SPITCH] = wv1.y; bs[6*SPITCH] = wv1.z; bs[7*SPITCH] = wv1.w;
            __syncthreads();
        }
    }

    // epilogue
#pragma unroll
    for (int i = 0; i < 8; i++) {
        const int m = bm + moff + i;
#pragma unroll
        for (int jp = 0; jp < 4; jp++) {
            float vlo, vhi;
            unpack2(acc2[i][jp], vlo, vhi);
            float vv[2] = {vlo, vhi};
#pragma unroll
            for (int q = 0; q < 2; q++) {
                const int n = bn + noff + jp * 2 + q;
                float v = vv[q];
                const long ci = (long)m * N + n;
                if (EPI == 2)      v = v + res[ci];
                else if (EPI == 3) v = gelu_f(v + bias[n]);
                else if (EPI == 4) v = v + bias[n] + res[ci];
                else if (EPI == 5) v = v + bias[n];
                C[ci] = v;
            }
        }
    }
}

// ---------------- small GEMM (bounds-checked 64x64x16): for N=80 / K=48 cases ----------------
// EPI: 0=none, 1=softplus(x+bias)
template <int EPI>
__global__ void __launch_bounds__(256) k_gemm64(const float* __restrict__ A, int lda,
                                                const float* __restrict__ W,
                                                const float* __restrict__ bias,
                                                float* __restrict__ C,
                                                int M, int N, int Kd) {
    __shared__ __align__(16) float As[16][64];
    __shared__ __align__(16) float Bs[16][64];
    int bm = blockIdx.y * 64;
    int bn = blockIdx.x * 64;
    int tid = threadIdx.x;
    int ty = tid >> 4, tx = tid & 15;

    int lrow = tid >> 2;
    int lk   = (tid & 3) * 4;
    int arow = bm + lrow; bool avalid = arow < M; if (!avalid) arow = M - 1;
    int wrow = bn + lrow; bool wvalid = wrow < N; if (!wvalid) wrow = N - 1;
    const float* Ap = A + (long)arow * lda + lk;
    const float* Wp = W + (long)wrow * Kd  + lk;

    float acc[4][4] = {};
    for (int kt = 0; kt < Kd; kt += 16) {
        float4 av = avalid ? *(const float4*)(Ap + kt) : make_float4(0.f, 0.f, 0.f, 0.f);
        float4 wv = wvalid ? *(const float4*)(Wp + kt) : make_float4(0.f, 0.f, 0.f, 0.f);
        As[lk + 0][lrow] = av.x; As[lk + 1][lrow] = av.y;
        As[lk + 2][lrow] = av.z; As[lk + 3][lrow] = av.w;
        Bs[lk + 0][lrow] = wv.x; Bs[lk + 1][lrow] = wv.y;
        Bs[lk + 2][lrow] = wv.z; Bs[lk + 3][lrow] = wv.w;
        __syncthreads();
#pragma unroll
        for (int kk = 0; kk < 16; kk++) {
            float4 a4 = *(const float4*)&As[kk][ty * 4];
            float4 b4 = *(const float4*)&Bs[kk][tx * 4];
            float am[4] = {a4.x, a4.y, a4.z, a4.w};
            float bn4[4] = {b4.x, b4.y, b4.z, b4.w};
#pragma unroll
            for (int i = 0; i < 4; i++)
#pragma unroll
                for (int j = 0; j < 4; j++)
                    acc[i][j] = fmaf(am[i], bn4[j], acc[i][j]);
        }
        __syncthreads();
    }
#pragma unroll
    for (int i = 0; i < 4; i++) {
        int m = bm + ty * 4 + i;
        if (m >= M) continue;
#pragma unroll
        for (int j = 0; j < 4; j++) {
            int n = bn + tx * 4 + j;
            if (n >= N) continue;
            float v = acc[i][j];
            long ci = (long)m * N + n;
            if (EPI == 1) v = softplus_f(v + bias[n]);
            C[ci] = v;
        }
    }
}

// ---------------- host orchestration ----------------
extern "C" void kernel_launch(void* const* d_in, const int* in_sizes, int n_in,
                              void* d_out, int out_size) {
    const int*   tokens  = (const int*)  d_in[0];
    const int*   tsteps  = (const int*)  d_in[1];
    const float* tok_emb = (const float*)d_in[2];
    const float* time_w1 = (const float*)d_in[3];
    const float* time_b1 = (const float*)d_in[4];
    const float* time_w2 = (const float*)d_in[5];
    const float* time_b2 = (const float*)d_in[6];
    const float* ln1_g   = (const float*)d_in[7];
    const float* ln1_b   = (const float*)d_in[8];
    const float* z_w     = (const float*)d_in[9];
    const float* p_w     = (const float*)d_in[10];
    const float* conv_w  = (const float*)d_in[11];
    const float* dtp_w   = (const float*)d_in[12];
    const float* dtp_b   = (const float*)d_in[13];
    const float* A_log   = (const float*)d_in[14];
    const float* D_param = (const float*)d_in[15];
    const float* out_w   = (const float*)d_in[16];
    const float* ln2_g   = (const float*)d_in[17];
    const float* ln2_b   = (const float*)d_in[18];
    const float* mlp_w1  = (const float*)d_in[19];
    const float* mlp_b1  = (const float*)d_in[20];
    const float* mlp_w2  = (const float*)d_in[21];
    const float* mlp_b2  = (const float*)d_in[22];
    const float* lnout_g = (const float*)d_in[23];
    const float* lnout_b = (const float*)d_in[24];
    const float* head_w  = (const float*)d_in[25];
    const float* head_b  = (const float*)d_in[26];
    float* out = (float*)d_out;

    float *px, *pxn, *pz, *pdt, *pu, *py, *pp, *phid, *psemb, *pthid, *ptemb;
    cudaGetSymbolAddress((void**)&px,    g_x);
    cudaGetSymbolAddress((void**)&pxn,   g_xn);
    cudaGetSymbolAddress((void**)&pz,    g_z);
    cudaGetSymbolAddress((void**)&pdt,   g_dt);
    cudaGetSymbolAddress((void**)&pu,    g_u);
    cudaGetSymbolAddress((void**)&py,    g_y);
    cudaGetSymbolAddress((void**)&pp,    g_p);
    cudaGetSymbolAddress((void**)&phid,  g_hid);
    cudaGetSymbolAddress((void**)&psemb, g_semb);
    cudaGetSymbolAddress((void**)&pthid, g_thid);
    cudaGetSymbolAddress((void**)&ptemb, g_temb);

    const int TPB = 256;
    k_semb <<<(B_*E_ + TPB - 1) / TPB, TPB>>>(tsteps, psemb);
    k_time1<<<(B_*H_ + TPB - 1) / TPB, TPB>>>(psemb, time_w1, time_b1, pthid);
    k_time2<<<(B_*E_ + TPB - 1) / TPB, TPB>>>(pthid, time_w2, time_b2, ptemb);
    k_embed<<<(ML*E_) / TPB, TPB>>>(tokens, tok_emb, ptemb, px);

    dim3 gE(E_ / 128, ML / 128);     // (6, 16)
    dim3 gH(H_ / 128, ML / 128);     // (24, 16)
    dim3 gV(V_ / 128, ML / 128);     // (250, 16)
    dim3 gP((P_ + 63) / 64, ML / 64);
    dim3 gDt(E_ / 64, ML / 64);

    for (int i = 0; i < DEP; i++) {
        k_ln<<<ML, TPB>>>(px, ln1_g + i * E_, ln1_b + i * E_, pxn);
        k_gemm128<0><<<gE, TPB>>>(pxn, E_, z_w + (long)i * E_ * E_, E_, nullptr, nullptr, pz, ML, E_, E_);
        k_gemm64<0><<<gP, TPB>>>(pxn, E_, p_w + (long)i * P_ * E_, nullptr, pp, ML, P_, E_);
        k_gemm64<1><<<gDt, TPB>>>(pp, P_, dtp_w + (long)i * E_ * R_, dtp_b + i * E_, pdt, ML, E_, R_);
        k_conv_silu<<<(ML*E_) / TPB, TPB>>>(pxn, conv_w + (long)i * E_ * KC, pu);
        k_scan<<<(B_*E_*NST) / TPB, TPB>>>(pdt, pu, pp, pz,
                                           A_log + (long)i * E_ * NST, D_param + i * E_, py);
        k_gemm128<2><<<gE, TPB>>>(py, E_, out_w + (long)i * E_ * E_, E_, nullptr, px, px, ML, E_, E_);
        k_ln<<<ML, TPB>>>(px, ln2_g + i * E_, ln2_b + i * E_, pxn);
        k_gemm128<3><<<gH, TPB>>>(pxn, E_, mlp_w1 + (long)i * H_ * E_, E_, mlp_b1 + i * H_, nullptr, phid, ML, H_, E_);
        k_gemm128<4><<<gE, TPB>>>(phid, H_, mlp_w2 + (long)i * E_ * H_, H_, mlp_b2 + i * E_, px, px, ML, E_, H_);
    }

    k_ln<<<ML, TPB>>>(px, lnout_g, lnout_b, pxn);
    k_gemm128<5><<<gV, TPB>>>(pxn, E_, head_w, E_, head_b, nullptr, out, ML, V_, E_);
}

// round 17
// speedup vs baseline: 1.3963x; 1.3963x over previous
#include <cuda_runtime.h>
#include <cuda_bf16.h>
#include <math.h>
#include <stdint.h>

// ---------------- problem constants ----------------
#define B_    2
#define L_    1024
#define E_    768
#define NST   16
#define KC    4
#define R_    48
#define P_    80          // R + 2N
#define H_    3072
#define V_    32000
#define DEP   4
#define ML    (B_*L_)     // 2048 rows

// ---------------- scratch (static device, no allocs) ----------------
__device__ float g_x  [ML*E_];
__device__ float g_xn [ML*E_];
__device__ float g_z  [ML*E_];
__device__ float g_dt [ML*E_];
__device__ float g_u  [ML*E_];
__device__ float g_y  [ML*E_];
__device__ float g_p  [ML*P_];
__device__ float g_hid[ML*H_];
__device__ float g_semb[B_*E_];
__device__ float g_thid[B_*H_];
__device__ float g_temb[B_*E_];
// bf16 3K-split buffers (A: activations, W: weights)
__device__ __nv_bfloat16 g_a3[(long)ML * 3 * H_];
__device__ __nv_bfloat16 g_w3[(long)V_ * 3 * E_];

// ---------------- helpers ----------------
__device__ __forceinline__ float silu_f(float x)  { return x / (1.f + expf(-x)); }
__device__ __forceinline__ float gelu_f(float x)  { return 0.5f * x * (1.f + erff(x * 0.70710678118654752f)); }
__device__ __forceinline__ float softplus_f(float x) { return (x > 20.f) ? x : log1pf(expf(x)); }

__device__ __forceinline__ uint32_t smem_to_u32(const void* p) {
    uint32_t a;
    asm("{ .reg .u64 t; cvta.to.shared.u64 t, %1; cvt.u32.u64 %0, t; }" : "=r"(a) : "l"(p));
    return a;
}

// ldmatrix x4 (sm_75+)
#define LDSM_X4(r0, r1, r2, r3, addr) \
    asm volatile("ldmatrix.sync.aligned.m8n8.x4.shared.b16 {%0,%1,%2,%3}, [%4];" \
        : "=r"(r0), "=r"(r1), "=r"(r2), "=r"(r3) : "r"(addr))

// mma m16n8k16 bf16 (sm_80+)
#define MMA_BF16(c, a0, a1, a2, a3, b0, b1) \
    asm volatile("mma.sync.aligned.m16n8k16.row.col.f32.bf16.bf16.f32 " \
        "{%0,%1,%2,%3}, {%4,%5,%6,%7}, {%8,%9}, {%0,%1,%2,%3};" \
        : "+f"((c).x), "+f"((c).y), "+f"((c).z), "+f"((c).w) \
        : "r"(a0), "r"(a1), "r"(a2), "r"(a3), "r"(b0), "r"(b1))

// ---------------- small kernels ----------------
__global__ void k_semb(const int* __restrict__ ts, float* __restrict__ semb) {
    int idx = blockIdx.x * blockDim.x + threadIdx.x;
    if (idx >= B_ * E_) return;
    int b = idx / E_, e = idx % E_;
    float t = (float)ts[b];
    const int half = E_ / 2;
    float v;
    if (e < half) {
        float f = expf(-logf(10000.f) * (float)e / (float)half);
        v = sinf(t * f);
    } else {
        float f = expf(-logf(10000.f) * (float)(e - half) / (float)half);
        v = cosf(t * f);
    }
    semb[idx] = v;
}

__global__ void k_time1(const float* __restrict__ semb, const float* __restrict__ w1,
                        const float* __restrict__ b1, float* __restrict__ hid) {
    int idx = blockIdx.x * blockDim.x + threadIdx.x;
    if (idx >= B_ * H_) return;
    int b = idx / H_, h = idx % H_;
    const float* sr = semb + b * E_;
    const float* wr = w1 + (long)h * E_;
    float s = b1[h];
    for (int e = 0; e < E_; e++) s += sr[e] * wr[e];
    hid[idx] = silu_f(s);
}

__global__ void k_time2(const float* __restrict__ hid, const float* __restrict__ w2,
                        const float* __restrict__ b2, float* __restrict__ temb) {
    int idx = blockIdx.x * blockDim.x + threadIdx.x;
    if (idx >= B_ * E_) return;
    int b = idx / E_, e = idx % E_;
    const float* hr = hid + b * H_;
    const float* wr = w2 + (long)e * H_;
    float s = b2[e];
    for (int h = 0; h < H_; h++) s += hr[h] * wr[h];
    temb[idx] = s;
}

__global__ void k_embed(const int* __restrict__ tok, const float* __restrict__ emb,
                        const float* __restrict__ temb, float* __restrict__ x) {
    long idx = (long)blockIdx.x * blockDim.x + threadIdx.x;
    if (idx >= (long)ML * E_) return;
    int e  = (int)(idx % E_);
    int bl = (int)(idx / E_);
    int b  = bl / L_;
    int t  = tok[bl];
    x[idx] = emb[(long)t * E_ + e] + temb[b * E_ + e];
}

__global__ void k_ln(const float* __restrict__ x, const float* __restrict__ g,
                     const float* __restrict__ bta, float* __restrict__ o) {
    __shared__ float red[256];
    int row = blockIdx.x;
    int tid = threadIdx.x;
    const float* xr = x + (long)row * E_;
    float v[3];
    float s = 0.f;
#pragma unroll
    for (int i = 0; i < 3; i++) { v[i] = xr[tid + i * 256]; s += v[i]; }
    red[tid] = s; __syncthreads();
    for (int st = 128; st > 0; st >>= 1) { if (tid < st) red[tid] += red[tid + st]; __syncthreads(); }
    float mu = red[0] / (float)E_;
    __syncthreads();
    float s2 = 0.f;
#pragma unroll
    for (int i = 0; i < 3; i++) { float d = v[i] - mu; s2 += d * d; }
    red[tid] = s2; __syncthreads();
    for (int st = 128; st > 0; st >>= 1) { if (tid < st) red[tid] += red[tid + st]; __syncthreads(); }
    float rs = rsqrtf(red[0] / (float)E_ + 1e-5f);
    float* orow = o + (long)row * E_;
#pragma unroll
    for (int i = 0; i < 3; i++) {
        int c = tid + i * 256;
        orow[c] = (v[i] - mu) * rs * g[c] + bta[c];
    }
}

__global__ void k_conv_silu(const float* __restrict__ xn, const float* __restrict__ w,
                            float* __restrict__ u) {
    long idx = (long)blockIdx.x * blockDim.x + threadIdx.x;
    if (idx >= (long)ML * E_) return;
    int e  = (int)(idx % E_);
    int bl = (int)(idx / E_);
    int l  = bl % L_;
    const float* xp = xn + idx;
    float s = 0.f;
#pragma unroll
    for (int k = 0; k < KC; k++) {
        int ll = l - (KC - 1) + k;
        if (ll >= 0) s += w[e * KC + k] * xp[(long)(k - (KC - 1)) * E_];
    }
    u[idx] = silu_f(s);
}

// ---------------- SSM scan: 16 threads per (b,e) channel ----------------
__global__ void k_scan(const float* __restrict__ dt, const float* __restrict__ u,
                       const float* __restrict__ p,  const float* __restrict__ z,
                       const float* __restrict__ A_log, const float* __restrict__ Dp,
                       float* __restrict__ y) {
    int tid = blockIdx.x * blockDim.x + threadIdx.x;
    if (tid >= B_ * E_ * NST) return;
    int g  = tid & 15;
    int ch = tid >> 4;
    int e  = ch % E_;
    int b  = ch / E_;

    float Av  = -expf(A_log[e * NST + g]);
    float iAv = 1.f / (Av + 1e-10f);
    bool  smA = fabsf(Av) < 1e-5f;
    float Dv  = Dp[e];

    const float* dtp = dt + (long)b * L_ * E_ + e;
    const float* up  = u  + (long)b * L_ * E_ + e;
    const float* zp  = z  + (long)b * L_ * E_ + e;
    const float* cp  = p  + (long)b * L_ * P_ + (R_ + NST) + g;
    float*       yp  = y  + (long)b * L_ * E_ + e;

    float cd = dtp[0];
    float cu = up[0];
    float cz = zp[0];
    float ccv = cp[0];

    float a  = __expf(cd * Av);
    float bv = smA ? cd : (a - 1.f) * iAv;
    float h  = bv * cu;

    float s = ccv * h;
    s += __shfl_xor_sync(0xffffffffu, s, 1);
    s += __shfl_xor_sync(0xffffffffu, s, 2);
    s += __shfl_xor_sync(0xffffffffu, s, 4);
    s += __shfl_xor_sync(0xffffffffu, s, 8);
    if (g == 0) yp[0] = (s + cu * Dv) * silu_f(cz);
    float pu = cu;

    for (int t = 1; t < L_; t++) {
        float nd = dtp[(long)t * E_];
        float nu = up [(long)t * E_];
        float nz = zp [(long)t * E_];
        float nc = cp [(long)t * P_];
        h = fmaf(a, h, bv * pu);
        float sv = nc * h;
        sv += __shfl_xor_sync(0xffffffffu, sv, 1);
        sv += __shfl_xor_sync(0xffffffffu, sv, 2);
        sv += __shfl_xor_sync(0xffffffffu, sv, 4);
        sv += __shfl_xor_sync(0xffffffffu, sv, 8);
        if (g == 0) yp[(long)t * E_] = (sv + nu * Dv) * silu_f(nz);
        pu = nu;
        a  = __expf(nd * Av);
        bv = smA ? nd : (a - 1.f) * iAv;
    }
}

// ---------------- bf16 hi/lo 3K-split conversion ----------------
// A: [hi | hi | lo]; B: [hi | lo | hi]  =>  sum = hi*hi + hi*lo + lo*hi
__global__ void k_cvt3_a(const float* __restrict__ X, __nv_bfloat16* __restrict__ X3,
                         long total, int K) {
    long idx = (long)blockIdx.x * blockDim.x + threadIdx.x;
    if (idx >= total) return;
    long r = idx / K;
    int  k = (int)(idx - r * K);
    float v = X[idx];
    __nv_bfloat16 hi = __float2bfloat16(v);
    __nv_bfloat16 lo = __float2bfloat16(v - __bfloat162float(hi));
    __nv_bfloat16* row = X3 + r * (3L * K);
    row[k] = hi; row[K + k] = hi; row[2L * K + k] = lo;
}
__global__ void k_cvt3_b(const float* __restrict__ X, __nv_bfloat16* __restrict__ X3,
                         long total, int K) {
    long idx = (long)blockIdx.x * blockDim.x + threadIdx.x;
    if (idx >= total) return;
    long r = idx / K;
    int  k = (int)(idx - r * K);
    float v = X[idx];
    __nv_bfloat16 hi = __float2bfloat16(v);
    __nv_bfloat16 lo = __float2bfloat16(v - __bfloat162float(hi));
    __nv_bfloat16* row = X3 + r * (3L * K);
    row[k] = hi; row[K + k] = lo; row[2L * K + k] = hi;
}

// ================= mma.sync bf16 GEMM: 128x128 CTA tile, warp 32x64, K-chunk 64 =================
// C[m,n] = sum_k A3[m,k]*B3[n,k]; A3/B3 bf16 row-major (K-contiguous); M,N % 128 == 0; Kp % 64 == 0.
// EPI: 0=none, 2=x+res, 3=gelu(x+bias), 4=x+bias+res, 5=x+bias
#define APITCH_B 144                    // bytes per smem row (72 bf16): LDSM conflict-light
#define TILE_B   (128 * APITCH_B)       // 18432 bytes per operand tile
#define MM_SMEM  (4 * TILE_B)           // double buffer x {A,B} = 73728
template <int EPI>
__global__ void __launch_bounds__(256) k_gemm_mma(const __nv_bfloat16* __restrict__ A3, long lda,
                                                  const __nv_bfloat16* __restrict__ B3, long ldb,
                                                  const float* __restrict__ bias,
                                                  const float* __restrict__ res,
                                                  float* __restrict__ C,
                                                  int M, int N, int Kp) {
    extern __shared__ __align__(16) char smem[];
    const uint32_t sb = smem_to_u32(smem);
    const int tid  = threadIdx.x;
    const int wid  = tid >> 5;
    const int lane = tid & 31;
    const int bm = blockIdx.x * 128;
    const int bn = blockIdx.y * 128;
    const int m_warp = (wid & 3) * 32;
    const int n_warp = (wid >> 2) * 64;

    // gmem load mapping: 8 segs x 16B per 128B k-row; 32 rows per pass, 4 passes
    const int seg   = tid & 7;
    const int rbase = tid >> 3;
    const __nv_bfloat16* Ag = A3 + (long)(bm + rbase) * lda + seg * 8;
    const __nv_bfloat16* Bg = B3 + (long)(bn + rbase) * ldb + seg * 8;
    const uint32_t s_row = rbase * APITCH_B + seg * 16;

    // per-lane ldmatrix offsets (within a tile)
    const uint32_t a_lm = (uint32_t)(m_warp + (lane & 15)) * APITCH_B + ((lane >> 4) * 8) * 2;
    const uint32_t b_lm = (uint32_t)(n_warp + (lane & 7) + ((lane >> 4) * 8)) * APITCH_B + (((lane >> 3) & 1) * 8) * 2;

    float4 acc[2][8];
#pragma unroll
    for (int i = 0; i < 2; i++)
#pragma unroll
        for (int j = 0; j < 8; j++) acc[i][j] = make_float4(0.f, 0.f, 0.f, 0.f);

    const int nt = Kp >> 6;
    // prologue: load chunk 0 into buffer 0
#pragma unroll
    for (int p = 0; p < 4; p++) {
        *(uint4*)(smem + p * 32 * APITCH_B + s_row)          = *(const uint4*)(Ag + (long)p * 32 * lda);
        *(uint4*)(smem + TILE_B + p * 32 * APITCH_B + s_row) = *(const uint4*)(Bg + (long)p * 32 * ldb);
    }
    __syncthreads();

    for (int kt = 0; kt < nt; kt++) {
        // prefetch next chunk into the other buffer
        if (kt + 1 < nt) {
            char* dst = smem + ((kt + 1) & 1) * (2 * TILE_B);
            const __nv_bfloat16* Ak = Ag + (long)(kt + 1) * 64;
            const __nv_bfloat16* Bk = Bg + (long)(kt + 1) * 64;
#pragma unroll
            for (int p = 0; p < 4; p++) {
                *(uint4*)(dst + p * 32 * APITCH_B + s_row)          = *(const uint4*)(Ak + (long)p * 32 * lda);
                *(uint4*)(dst + TILE_B + p * 32 * APITCH_B + s_row) = *(const uint4*)(Bk + (long)p * 32 * ldb);
            }
        }
        // compute current chunk
        const uint32_t abuf = sb + (kt & 1) * (2 * TILE_B);
        const uint32_t bbuf = abuf + TILE_B;
#pragma unroll
        for (int kk = 0; kk < 4; kk++) {
            uint32_t af[2][4];
            LDSM_X4(af[0][0], af[0][1], af[0][2], af[0][3], abuf + a_lm + kk * 32);
            LDSM_X4(af[1][0], af[1][1], af[1][2], af[1][3], abuf + a_lm + 16 * APITCH_B + kk * 32);
            uint32_t bf[8][2];
#pragma unroll
            for (int g = 0; g < 4; g++) {
                uint32_t r0, r1, r2, r3;
                LDSM_X4(r0, r1, r2, r3, bbuf + b_lm + g * 16 * APITCH_B + kk * 32);
                bf[g * 2 + 0][0] = r0; bf[g * 2 + 0][1] = r1;
                bf[g * 2 + 1][0] = r2; bf[g * 2 + 1][1] = r3;
            }
#pragma unroll
            for (int mi = 0; mi < 2; mi++)
#pragma unroll
                for (int ni = 0; ni < 8; ni++)
                    MMA_BF16(acc[mi][ni], af[mi][0], af[mi][1], af[mi][2], af[mi][3],
                             bf[ni][0], bf[ni][1]);
        }
        __syncthreads();
    }

    // epilogue: thread T holds C rows m+T/4 (+8), cols n + 2*(T%4) (+1)
    const int gq = lane >> 2;
    const int tq = lane & 3;
#pragma unroll
    for (int mi = 0; mi < 2; mi++) {
        const int r0 = bm + m_warp + mi * 16 + gq;
        const int r1 = r0 + 8;
#pragma unroll
        for (int ni = 0; ni < 8; ni++) {
            const int cc = bn + n_warp + ni * 8 + 2 * tq;
            float v0 = acc[mi][ni].x, v1 = acc[mi][ni].y;   // row r0, cols cc, cc+1
            float v2 = acc[mi][ni].z, v3 = acc[mi][ni].w;   // row r1
            const long i00 = (long)r0 * N + cc;
            const long i10 = (long)r1 * N + cc;
            if (EPI == 2) {
                v0 += res[i00]; v1 += res[i00 + 1]; v2 += res[i10]; v3 += res[i10 + 1];
            } else if (EPI == 3) {
                float b0 = bias[cc], b1 = bias[cc + 1];
                v0 = gelu_f(v0 + b0); v1 = gelu_f(v1 + b1);
                v2 = gelu_f(v2 + b0); v3 = gelu_f(v3 + b1);
            } else if (EPI == 4) {
                float b0 = bias[cc], b1 = bias[cc + 1];
                v0 += b0 + res[i00]; v1 += b1 + res[i00 + 1];
                v2 += b0 + res[i10]; v3 += b1 + res[i10 + 1];
            } else if (EPI == 5) {
                v0 += bias[cc]; v1 += bias[cc + 1];
                v2 += bias[cc]; v3 += bias[cc + 1];
            }
            *(float2*)(C + i00) = make_float2(v0, v1);
            *(float2*)(C + i10) = make_float2(v2, v3);
        }
    }
}

// ---------------- small SIMT GEMM (bounds-checked 64x64x16): N=80 / K=48 cases ----------------
// EPI: 0=none, 1=softplus(x+bias)
template <int EPI>
__global__ void __launch_bounds__(256) k_gemm64(const float* __restrict__ A, int lda,
                                                const float* __restrict__ W,
                                                const float* __restrict__ bias,
                                                float* __restrict__ C,
                                                int M, int N, int Kd) {
    __shared__ __align__(16) float As[16][64];
    __shared__ __align__(16) float Bs[16][64];
    int bm = blockIdx.y * 64;
    int bn = blockIdx.x * 64;
    int tid = threadIdx.x;
    int ty = tid >> 4, tx = tid & 15;

    int lrow = tid >> 2;
    int lk   = (tid & 3) * 4;
    int arow = bm + lrow; bool avalid = arow < M; if (!avalid) arow = M - 1;
    int wrow = bn + lrow; bool wvalid = wrow < N; if (!wvalid) wrow = N - 1;
    const float* Ap = A + (long)arow * lda + lk;
    const float* Wp = W + (long)wrow * Kd  + lk;

    float acc[4][4] = {};
    for (int kt = 0; kt < Kd; kt += 16) {
        float4 av = avalid ? *(const float4*)(Ap + kt) : make_float4(0.f, 0.f, 0.f, 0.f);
        float4 wv = wvalid ? *(const float4*)(Wp + kt) : make_float4(0.f, 0.f, 0.f, 0.f);
        As[lk + 0][lrow] = av.x; As[lk + 1][lrow] = av.y;
        As[lk + 2][lrow] = av.z; As[lk + 3][lrow] = av.w;
        Bs[lk + 0][lrow] = wv.x; Bs[lk + 1][lrow] = wv.y;
        Bs[lk + 2][lrow] = wv.z; Bs[lk + 3][lrow] = wv.w;
        __syncthreads();
#pragma unroll
        for (int kk = 0; kk < 16; kk++) {
            float4 a4 = *(const float4*)&As[kk][ty * 4];
            float4 b4 = *(const float4*)&Bs[kk][tx * 4];
            float am[4] = {a4.x, a4.y, a4.z, a4.w};
            float bn4[4] = {b4.x, b4.y, b4.z, b4.w};
#pragma unroll
            for (int i = 0; i < 4; i++)
#pragma unroll
                for (int j = 0; j < 4; j++)
                    acc[i][j] = fmaf(am[i], bn4[j], acc[i][j]);
        }
        __syncthreads();
    }
#pragma unroll
    for (int i = 0; i < 4; i++) {
        int m = bm + ty * 4 + i;
        if (m >= M) continue;
#pragma unroll
        for (int j = 0; j < 4; j++) {
            int n = bn + tx * 4 + j;
            if (n >= N) continue;
            float v = acc[i][j];
            long ci = (long)m * N + n;
            if (EPI == 1) v = softplus_f(v + bias[n]);
            C[ci] = v;
        }
    }
}

// ---------------- host orchestration ----------------
static inline int cdiv(long a, int b) { return (int)((a + b - 1) / b); }

extern "C" void kernel_launch(void* const* d_in, const int* in_sizes, int n_in,
                              void* d_out, int out_size) {
    const int*   tokens  = (const int*)  d_in[0];
    const int*   tsteps  = (const int*)  d_in[1];
    const float* tok_emb = (const float*)d_in[2];
    const float* time_w1 = (const float*)d_in[3];
    const float* time_b1 = (const float*)d_in[4];
    const float* time_w2 = (const float*)d_in[5];
    const float* time_b2 = (const float*)d_in[6];
    const float* ln1_g   = (const float*)d_in[7];
    const float* ln1_b   = (const float*)d_in[8];
    const float* z_w     = (const float*)d_in[9];
    const float* p_w     = (const float*)d_in[10];
    const float* conv_w  = (const float*)d_in[11];
    const float* dtp_w   = (const float*)d_in[12];
    const float* dtp_b   = (const float*)d_in[13];
    const float* A_log   = (const float*)d_in[14];
    const float* D_param = (const float*)d_in[15];
    const float* out_w   = (const float*)d_in[16];
    const float* ln2_g   = (const float*)d_in[17];
    const float* ln2_b   = (const float*)d_in[18];
    const float* mlp_w1  = (const float*)d_in[19];
    const float* mlp_b1  = (const float*)d_in[20];
    const float* mlp_w2  = (const float*)d_in[21];
    const float* mlp_b2  = (const float*)d_in[22];
    const float* lnout_g = (const float*)d_in[23];
    const float* lnout_b = (const float*)d_in[24];
    const float* head_w  = (const float*)d_in[25];
    const float* head_b  = (const float*)d_in[26];
    float* out = (float*)d_out;

    float *px, *pxn, *pz, *pdt, *pu, *py, *pp, *phid, *psemb, *pthid, *ptemb;
    __nv_bfloat16 *pa3, *pw3;
    cudaGetSymbolAddress((void**)&px,    g_x);
    cudaGetSymbolAddress((void**)&pxn,   g_xn);
    cudaGetSymbolAddress((void**)&pz,    g_z);
    cudaGetSymbolAddress((void**)&pdt,   g_dt);
    cudaGetSymbolAddress((void**)&pu,    g_u);
    cudaGetSymbolAddress((void**)&py,    g_y);
    cudaGetSymbolAddress((void**)&pp,    g_p);
    cudaGetSymbolAddress((void**)&phid,  g_hid);
    cudaGetSymbolAddress((void**)&psemb, g_semb);
    cudaGetSymbolAddress((void**)&pthid, g_thid);
    cudaGetSymbolAddress((void**)&ptemb, g_temb);
    cudaGetSymbolAddress((void**)&pa3,   g_a3);
    cudaGetSymbolAddress((void**)&pw3,   g_w3);

    cudaFuncSetAttribute(k_gemm_mma<0>, cudaFuncAttributeMaxDynamicSharedMemorySize, MM_SMEM);
    cudaFuncSetAttribute(k_gemm_mma<2>, cudaFuncAttributeMaxDynamicSharedMemorySize, MM_SMEM);
    cudaFuncSetAttribute(k_gemm_mma<3>, cudaFuncAttributeMaxDynamicSharedMemorySize, MM_SMEM);
    cudaFuncSetAttribute(k_gemm_mma<4>, cudaFuncAttributeMaxDynamicSharedMemorySize, MM_SMEM);
    cudaFuncSetAttribute(k_gemm_mma<5>, cudaFuncAttributeMaxDynamicSharedMemorySize, MM_SMEM);

    const int TPB = 256;
    k_semb <<<(B_*E_ + TPB - 1) / TPB, TPB>>>(tsteps, psemb);
    k_time1<<<(B_*H_ + TPB - 1) / TPB, TPB>>>(psemb, time_w1, time_b1, pthid);
    k_time2<<<(B_*E_ + TPB - 1) / TPB, TPB>>>(pthid, time_w2, time_b2, ptemb);
    k_embed<<<(ML*E_) / TPB, TPB>>>(tokens, tok_emb, ptemb, px);

    dim3 gE (ML / 128, E_ / 128);     // m-tile fast: consecutive CTAs reuse the B panel in L2
    dim3 gH (ML / 128, H_ / 128);
    dim3 gV (ML / 128, V_ / 128);
    dim3 gP ((P_ + 63) / 64, ML / 64);
    dim3 gDt(E_ / 64, ML / 64);

    const long nXE = (long)ML * E_;
    const long nXH = (long)ML * H_;

    for (int i = 0; i < DEP; i++) {
        k_ln<<<ML, TPB>>>(px, ln1_g + i * E_, ln1_b + i * E_, pxn);
        // z = xn @ z_w^T (tensor)
        k_cvt3_a<<<cdiv(nXE, TPB), TPB>>>(pxn, pa3, nXE, E_);
        k_cvt3_b<<<cdiv((long)E_ * E_, TPB), TPB>>>(z_w + (long)i * E_ * E_, pw3, (long)E_ * E_, E_);
        k_gemm_mma<0><<<gE, TPB, MM_SMEM>>>(pa3, 3 * E_, pw3, 3 * E_, nullptr, nullptr, pz, ML, E_, 3 * E_);
        // params, dt (small SIMT)
        k_gemm64<0><<<gP, TPB>>>(pxn, E_, p_w + (long)i * P_ * E_, nullptr, pp, ML, P_, E_);
        k_gemm64<1><<<gDt, TPB>>>(pp, P_, dtp_w + (long)i * E_ * R_, dtp_b + i * E_, pdt, ML, E_, R_);
        k_conv_silu<<<(ML*E_) / TPB, TPB>>>(pxn, conv_w + (long)i * E_ * KC, pu);
        k_scan<<<(B_*E_*NST) / TPB, TPB>>>(pdt, pu, pp, pz,
                                           A_log + (long)i * E_ * NST, D_param + i * E_, py);
        // x += y @ out_w^T (tensor)
        k_cvt3_a<<<cdiv(nXE, TPB), TPB>>>(py, pa3, nXE, E_);
        k_cvt3_b<<<cdiv((long)E_ * E_, TPB), TPB>>>(out_w + (long)i * E_ * E_, pw3, (long)E_ * E_, E_);
        k_gemm_mma<2><<<gE, TPB, MM_SMEM>>>(pa3, 3 * E_, pw3, 3 * E_, nullptr, px, px, ML, E_, 3 * E_);
        // MLP
        k_ln<<<ML, TPB>>>(px, ln2_g + i * E_, ln2_b + i * E_, pxn);
        k_cvt3_a<<<cdiv(nXE, TPB), TPB>>>(pxn, pa3, nXE, E_);
        k_cvt3_b<<<cdiv((long)H_ * E_, TPB), TPB>>>(mlp_w1 + (long)i * H_ * E_, pw3, (long)H_ * E_, E_);
        k_gemm_mma<3><<<gH, TPB, MM_SMEM>>>(pa3, 3 * E_, pw3, 3 * E_, mlp_b1 + i * H_, nullptr, phid, ML, H_, 3 * E_);
        k_cvt3_a<<<cdiv(nXH, TPB), TPB>>>(phid, pa3, nXH, H_);
        k_cvt3_b<<<cdiv((long)E_ * H_, TPB), TPB>>>(mlp_w2 + (long)i * E_ * H_, pw3, (long)E_ * H_, H_);
        k_gemm_mma<4><<<gE, TPB, MM_SMEM>>>(pa3, 3 * H_, pw3, 3 * H_, mlp_b2 + i * E_, px, px, ML, E_, 3 * H_);
    }

    k_ln<<<ML, TPB>>>(px, lnout_g, lnout_b, pxn);
    k_cvt3_a<<<cdiv(nXE, TPB), TPB>>>(pxn, pa3, nXE, E_);
    k_cvt3_b<<<cdiv((long)V_ * E_, TPB), TPB>>>(head_w, pw3, (long)V_ * E_, E_);
    k_gemm_mma<5><<<gV, TPB, MM_SMEM>>>(pa3, 3 * E_, pw3, 3 * E_, head_b, nullptr, out, ML, V_, 3 * E_);
}